// round 1
// baseline (speedup 1.0000x reference)
#include <cuda_runtime.h>

#define L_ 2048
#define E_ 256
#define H2_ 256
#define H4_ 1024
#define T_ 6
#define START_ 4
#define STOP_ 5
#define NEG_ (-10000.0f)

// Scratch (static __device__ arrays: allocation-free per harness rules)
__device__ float g_pre[2][L_][H4_];    // 16 MB: input projections per direction
__device__ float g_h[2][L_][H2_];      // 4 MB: hidden states (position-indexed)
__device__ float g_feats[L_][T_];      // 48 KB: emission scores

// ---------------------------------------------------------------------------
// Kernel 1: pre[d][t][n] = sum_k embed[sent[t']][k] * Wih_d[n][k] + bih[n] + bhh[n]
// (t' reversed for the backward direction). 64x64 tile, BK=16, 4x4 microtile.
// ---------------------------------------------------------------------------
__global__ __launch_bounds__(256) void gemm_pre_kernel(
    const int* __restrict__ sent, const float* __restrict__ embed,
    const float* __restrict__ WihF, const float* __restrict__ bihF, const float* __restrict__ bhhF,
    const float* __restrict__ WihB, const float* __restrict__ bihB, const float* __restrict__ bhhB)
{
    const int d = blockIdx.z;
    const float* __restrict__ Wih = d ? WihB : WihF;
    const float* __restrict__ bih = d ? bihB : bihF;
    const float* __restrict__ bhh = d ? bhhB : bhhF;

    __shared__ __align__(16) float As[16][64];   // [k][m]
    __shared__ __align__(16) float Bs[16][64];   // [k][n]

    const int t0 = blockIdx.x * 64;
    const int n0 = blockIdx.y * 64;
    const int tid = threadIdx.x;
    const int tm = (tid & 15) * 4;
    const int tn = (tid >> 4) * 4;
    const int am = tid >> 2;         // 0..63
    const int ak = (tid & 3) * 4;    // 0,4,8,12

    const int tg = t0 + am;
    const int tp = d ? (L_ - 1 - tg) : tg;
    const float* arow = embed + (size_t)sent[tp] * E_;
    const float* brow = Wih + (size_t)(n0 + am) * E_;

    float acc[4][4];
    #pragma unroll
    for (int i = 0; i < 4; i++)
        #pragma unroll
        for (int j = 0; j < 4; j++) acc[i][j] = 0.f;

    for (int k0 = 0; k0 < E_; k0 += 16) {
        float4 av = *(const float4*)(arow + k0 + ak);
        float4 bv = *(const float4*)(brow + k0 + ak);
        __syncthreads();
        As[ak + 0][am] = av.x; As[ak + 1][am] = av.y;
        As[ak + 2][am] = av.z; As[ak + 3][am] = av.w;
        Bs[ak + 0][am] = bv.x; Bs[ak + 1][am] = bv.y;
        Bs[ak + 2][am] = bv.z; Bs[ak + 3][am] = bv.w;
        __syncthreads();
        #pragma unroll
        for (int kk = 0; kk < 16; kk++) {
            float a[4], b[4];
            *(float4*)a = *(const float4*)&As[kk][tm];
            *(float4*)b = *(const float4*)&Bs[kk][tn];
            #pragma unroll
            for (int i = 0; i < 4; i++)
                #pragma unroll
                for (int j = 0; j < 4; j++) acc[i][j] += a[i] * b[j];
        }
    }
    #pragma unroll
    for (int i = 0; i < 4; i++)
        #pragma unroll
        for (int j = 0; j < 4; j++) {
            int n = n0 + tn + j;
            g_pre[d][t0 + tm + i][n] = acc[i][j] + bih[n] + bhh[n];
        }
}

// ---------------------------------------------------------------------------
// Kernel 2: LSTM recurrence. One 8-CTA cluster per direction.
// Each CTA holds 128 rows of Whh in registers (packed f32x2, fma.rn.f32x2),
// broadcasts its z-slice to all cluster CTAs via DSMEM, one cluster.sync/step,
// and every CTA replicates the gate update (c state per-thread).
// ---------------------------------------------------------------------------
__device__ __forceinline__ void fma2(unsigned long long& d,
                                     unsigned long long a, unsigned long long b) {
    asm("fma.rn.f32x2 %0, %1, %2, %0;" : "+l"(d) : "l"(a), "l"(b));
}
__device__ __forceinline__ float lo32(unsigned long long v) {
    return __uint_as_float((unsigned)(v & 0xffffffffull));
}
__device__ __forceinline__ float hi32(unsigned long long v) {
    return __uint_as_float((unsigned)(v >> 32));
}

__global__ void __cluster_dims__(8, 1, 1) __launch_bounds__(256, 1)
lstm_kernel(const float* __restrict__ WhhF, const float* __restrict__ WhhB,
            const float* __restrict__ h0, const float* __restrict__ c0)
{
    __shared__ __align__(16) float h_sm[H2_];
    __shared__ float z_sm[2][H4_];   // double-buffered by step parity

    const int d = blockIdx.y;
    unsigned rank;
    asm("mov.u32 %0, %%cluster_ctarank;" : "=r"(rank));

    const int tid  = threadIdx.x;
    const int r    = tid >> 1;       // row within CTA slice (0..127)
    const int half = tid & 1;        // which 128-column half
    const int grow = (int)rank * 128 + r;   // global row in [0,1024)
    const float* __restrict__ Whh = d ? WhhB : WhhF;

    // Load weights: 128 floats per thread = 64 packed f32x2 register pairs
    unsigned long long w2[64];
    {
        const float* wrow = Whh + (size_t)grow * H2_ + half * 128;
        #pragma unroll
        for (int i = 0; i < 32; i++) {
            ulonglong2 v = *(const ulonglong2*)(wrow + 4 * i);
            w2[2 * i] = v.x; w2[2 * i + 1] = v.y;
        }
    }

    h_sm[tid] = h0[d * H2_ + tid];
    float c = c0[d * H2_ + tid];
    __syncthreads();

    const float* __restrict__ pre = &g_pre[d][0][0];
    const unsigned zloc0 = (unsigned)__cvta_generic_to_shared(&z_sm[0][grow]);
    const unsigned zloc1 = (unsigned)__cvta_generic_to_shared(&z_sm[1][grow]);
    const float* hb = h_sm + half * 128;

    for (int t = 0; t < L_; t++) {
        // prefetch the per-step input projection (even lanes own the row)
        float p = 0.f;
        if (!half) p = __ldg(pre + (size_t)t * H4_ + grow);

        // z slice: 128-wide partial dot, packed f32x2 FMAs, 4 indep chains
        unsigned long long a0 = 0, a1 = 0, a2 = 0, a3 = 0;
        #pragma unroll
        for (int i = 0; i < 16; i++) {
            ulonglong2 hv0 = *(const ulonglong2*)(hb + 8 * i);
            ulonglong2 hv1 = *(const ulonglong2*)(hb + 8 * i + 4);
            fma2(a0, w2[4 * i + 0], hv0.x);
            fma2(a1, w2[4 * i + 1], hv0.y);
            fma2(a2, w2[4 * i + 2], hv1.x);
            fma2(a3, w2[4 * i + 3], hv1.y);
        }
        float s = (lo32(a0) + hi32(a0)) + (lo32(a1) + hi32(a1))
                + (lo32(a2) + hi32(a2)) + (lo32(a3) + hi32(a3));
        s += __shfl_xor_sync(0xffffffffu, s, 1);   // combine the two halves

        if (!half) {
            float z = s + p;
            unsigned zloc = (t & 1) ? zloc1 : zloc0;
            #pragma unroll
            for (int cta = 0; cta < 8; cta++) {
                unsigned raddr;
                asm("mapa.shared::cluster.u32 %0, %1, %2;"
                    : "=r"(raddr) : "r"(zloc), "r"(cta));
                asm volatile("st.shared::cluster.f32 [%0], %1;"
                             :: "r"(raddr), "f"(z));
            }
        }

        asm volatile("barrier.cluster.arrive.aligned;" ::: "memory");
        asm volatile("barrier.cluster.wait.aligned;"   ::: "memory");

        // gate update, replicated in all CTAs (thread j owns state index j)
        const float* zb = z_sm[t & 1];
        float zi = zb[tid], zf = zb[H2_ + tid], zg = zb[2 * H2_ + tid], zo = zb[3 * H2_ + tid];
        float ig = 1.f / (1.f + __expf(-zi));
        float fg = 1.f / (1.f + __expf(-zf));
        float og = 1.f / (1.f + __expf(-zo));
        float gg = 2.f / (1.f + __expf(-2.f * zg)) - 1.f;   // tanh
        c = fg * c + ig * gg;
        float th = 2.f / (1.f + __expf(-2.f * c)) - 1.f;    // tanh
        float h = og * th;
        h_sm[tid] = h;
        if (rank == 0) {
            int pos = d ? (L_ - 1 - t) : t;
            g_h[d][pos][tid] = h;
        }
        __syncthreads();
    }
}

// ---------------------------------------------------------------------------
// Kernel 3: feats[p][tag] = concat(hf[p],hb[p]) . W_out[tag] + b_out[tag]
// One warp per position; 8 warps per block.
// ---------------------------------------------------------------------------
__global__ __launch_bounds__(256) void feats_kernel(
    const float* __restrict__ Wout, const float* __restrict__ bout)
{
    const int warp = threadIdx.x >> 5, lane = threadIdx.x & 31;
    const int p = blockIdx.x * 8 + warp;
    float x[16];
    #pragma unroll
    for (int i = 0; i < 8; i++) x[i] = g_h[0][p][lane + 32 * i];
    #pragma unroll
    for (int i = 0; i < 8; i++) x[8 + i] = g_h[1][p][lane + 32 * i];
    #pragma unroll
    for (int tag = 0; tag < T_; tag++) {
        const float* wrow = Wout + tag * (2 * H2_);
        float acc = 0.f;
        #pragma unroll
        for (int i = 0; i < 16; i++)
            acc += x[i] * wrow[(i < 8 ? 0 : 256) + lane + 32 * (i & 7)];
        #pragma unroll
        for (int o = 16; o > 0; o >>= 1) acc += __shfl_xor_sync(0xffffffffu, acc, o);
        if (lane == 0) g_feats[p][tag] = acc + bout[tag];
    }
}

// ---------------------------------------------------------------------------
// Kernel 4: gold path score (block reduce) + CRF forward scan.
// Scan: warp 0, lane n owns next-state n; fv replicated in all lanes;
// emissions staged through smem in 256-step chunks.
// ---------------------------------------------------------------------------
__global__ __launch_bounds__(256) void crf_kernel(
    const int* __restrict__ tags, const float* __restrict__ trans,
    float* __restrict__ out)
{
    __shared__ float red[256];
    __shared__ float em[256 * T_];
    const int tid = threadIdx.x;

    // gold score
    float g = 0.f;
    for (int i = tid; i < L_; i += 256) {
        int cur = tags[i];
        int prev = (i == 0) ? START_ : tags[i - 1];
        g += trans[cur * T_ + prev] + g_feats[i][cur];
    }
    if (tid == 0) g += trans[STOP_ * T_ + tags[L_ - 1]];
    red[tid] = g;
    __syncthreads();
    for (int s = 128; s > 0; s >>= 1) {
        if (tid < s) red[tid] += red[tid + s];
        __syncthreads();
    }

    // forward scan
    float fv0 = NEG_, fv1 = NEG_, fv2 = NEG_, fv3 = NEG_, fv4 = 0.f, fv5 = NEG_; // START=4
    float trr[T_] = {0, 0, 0, 0, 0, 0};
    const int ln = (tid < T_) ? tid : 0;
    if (tid < 32) {
        #pragma unroll
        for (int j = 0; j < T_; j++) trr[j] = trans[ln * T_ + j];
    }
    const float* ff = &g_feats[0][0];
    for (int ch = 0; ch < L_ / 256; ch++) {
        for (int i = tid; i < 256 * T_; i += 256) em[i] = ff[ch * 256 * T_ + i];
        __syncthreads();
        if (tid < 32) {
            for (int s = 0; s < 256; s++) {
                float v0 = fv0 + trr[0], v1 = fv1 + trr[1], v2 = fv2 + trr[2];
                float v3 = fv3 + trr[3], v4 = fv4 + trr[4], v5 = fv5 + trr[5];
                float m = fmaxf(fmaxf(fmaxf(v0, v1), fmaxf(v2, v3)), fmaxf(v4, v5));
                float sum = __expf(v0 - m) + __expf(v1 - m) + __expf(v2 - m)
                          + __expf(v3 - m) + __expf(v4 - m) + __expf(v5 - m);
                float rr = m + __logf(sum) + em[s * T_ + ln];
                fv0 = __shfl_sync(0xffffffffu, rr, 0);
                fv1 = __shfl_sync(0xffffffffu, rr, 1);
                fv2 = __shfl_sync(0xffffffffu, rr, 2);
                fv3 = __shfl_sync(0xffffffffu, rr, 3);
                fv4 = __shfl_sync(0xffffffffu, rr, 4);
                fv5 = __shfl_sync(0xffffffffu, rr, 5);
            }
        }
        __syncthreads();
    }

    if (tid == 0) {
        float v0 = fv0 + trans[STOP_ * T_ + 0];
        float v1 = fv1 + trans[STOP_ * T_ + 1];
        float v2 = fv2 + trans[STOP_ * T_ + 2];
        float v3 = fv3 + trans[STOP_ * T_ + 3];
        float v4 = fv4 + trans[STOP_ * T_ + 4];
        float v5 = fv5 + trans[STOP_ * T_ + 5];
        float m = fmaxf(fmaxf(fmaxf(v0, v1), fmaxf(v2, v3)), fmaxf(v4, v5));
        float sum = __expf(v0 - m) + __expf(v1 - m) + __expf(v2 - m)
                  + __expf(v3 - m) + __expf(v4 - m) + __expf(v5 - m);
        float fwd = m + __logf(sum);
        out[0] = fwd - red[0];
    }
}

// ---------------------------------------------------------------------------
extern "C" void kernel_launch(void* const* d_in, const int* in_sizes, int n_in,
                              void* d_out, int out_size)
{
    const int*   sentence = (const int*)d_in[0];
    const int*   tags     = (const int*)d_in[1];
    const float* embed    = (const float*)d_in[2];
    const float* Wih_f    = (const float*)d_in[3];
    const float* Whh_f    = (const float*)d_in[4];
    const float* bih_f    = (const float*)d_in[5];
    const float* bhh_f    = (const float*)d_in[6];
    const float* Wih_b    = (const float*)d_in[7];
    const float* Whh_b    = (const float*)d_in[8];
    const float* bih_b    = (const float*)d_in[9];
    const float* bhh_b    = (const float*)d_in[10];
    const float* h0       = (const float*)d_in[11];
    const float* c0       = (const float*)d_in[12];
    const float* W_out    = (const float*)d_in[13];
    const float* b_out    = (const float*)d_in[14];
    const float* trans    = (const float*)d_in[15];
    float* out = (float*)d_out;

    gemm_pre_kernel<<<dim3(L_ / 64, H4_ / 64, 2), 256>>>(
        sentence, embed, Wih_f, bih_f, bhh_f, Wih_b, bih_b, bhh_b);
    lstm_kernel<<<dim3(8, 2), 256>>>(Whh_f, Whh_b, h0, c0);
    feats_kernel<<<L_ / 8, 256>>>(W_out, b_out);
    crf_kernel<<<1, 256>>>(tags, trans, out);
}